// round 7
// baseline (speedup 1.0000x reference)
#include <cuda_runtime.h>
#include <cuda_bf16.h>
#include <cstdint>

#define NN   8192
#define DIN  512
#define DOUT 256
#define KSLICES 2
#define KSL  (NN / KSLICES)     // 4096 k per slice
#define KT   32                 // k per chunk
#define NCHUNK (KSL / KT)       // 128

// ---------------- scratch (__device__ globals: allocation-free rule) --------
__device__ float          g_hW  [(size_t)NN * DOUT];      // fp32 hW (for f1f2)
__device__ float          g_f1  [NN];
__device__ float          g_f2  [NN];
__device__ float          g_fmax;
__device__ unsigned short g_hWT [(size_t)DOUT * NN];      // hW^T fp16 [col][row]
__device__ float          g_np  [(size_t)KSLICES * NN * DOUT]; // partial numerators
__device__ float          g_zp  [KSLICES * NN];                // partial Z

// ---------------- helpers ---------------------------------------------------
__device__ __forceinline__ uint32_t smem_u32(const void* p) {
    uint32_t a;
    asm("{ .reg .u64 t; cvta.to.shared.u64 t, %1; cvt.u32.u64 %0, t; }"
        : "=r"(a) : "l"(p));
    return a;
}
__device__ __forceinline__ uint32_t sw128(uint32_t off) {
    return off ^ ((off >> 3) & 0x70);
}
// packs (lo, hi) -> low 16 = f16(lo), high 16 = f16(hi)
__device__ __forceinline__ unsigned pack_f16x2(float lo, float hi) {
    unsigned r;
    asm("cvt.rn.f16x2.f32 %0, %1, %2;" : "=r"(r) : "f"(hi), "f"(lo));
    return r;
}
__device__ __forceinline__ void cp16(uint32_t smem, const void* g) {
    asm volatile("cp.async.cg.shared.global [%0], [%1], 16;"
                 :: "r"(smem), "l"(g));
}
__device__ __forceinline__ void cp_commit() {
    asm volatile("cp.async.commit_group;");
}
__device__ __forceinline__ void cp_wait0() {
    asm volatile("cp.async.wait_group 0;" ::: "memory");
}
__device__ __forceinline__ void ldsm4(uint32_t* r, uint32_t addr) {
    asm volatile("ldmatrix.sync.aligned.m8n8.x4.shared.b16 {%0,%1,%2,%3}, [%4];"
                 : "=r"(r[0]), "=r"(r[1]), "=r"(r[2]), "=r"(r[3]) : "r"(addr));
}
__device__ __forceinline__ void mma16816(float* c, const uint32_t* a,
                                         uint32_t b0, uint32_t b1) {
    asm volatile(
        "mma.sync.aligned.m16n8k16.row.col.f32.f16.f16.f32 "
        "{%0,%1,%2,%3},{%4,%5,%6,%7},{%8,%9},{%0,%1,%2,%3};"
        : "+f"(c[0]), "+f"(c[1]), "+f"(c[2]), "+f"(c[3])
        : "r"(a[0]), "r"(a[1]), "r"(a[2]), "r"(a[3]), "r"(b0), "r"(b1));
}

// ---------------------------------------------------------------------------
// Kernel A: g_hW = h @ W  (fp32)  +  epilogue: g_hWT fp16 (transposed)
// 128x64 tile, 256 threads, 8x4 micro-tile.
// ---------------------------------------------------------------------------
__global__ __launch_bounds__(256) void k_gemm_hw(
    const float* __restrict__ h, const float* __restrict__ W)
{
    __shared__ float As[32][128];  // [k][m] 16 KB
    __shared__ float Bs[32][64];   // [k][n]  8 KB

    const int tid = threadIdx.x;
    const int c0  = blockIdx.x * 64;
    const int i0  = blockIdx.y * 128;
    const int tx  = tid & 15;            // 4 cols
    const int ty  = tid >> 4;            // 8 rows

    const int li  = tid >> 1;            // 0..127 A-load row
    const int lk  = (tid & 1) * 16;      // A-load k base (16 k's)

    const int bk  = tid >> 3;            // 0..31  B-load k
    const int bc  = (tid & 7) * 8;       // B-load col (8 cols)

    float acc[8][4] = {};

    for (int k0 = 0; k0 < DIN; k0 += 32) {
        float4 a0 = *(const float4*)&h[(i0 + li) * DIN + k0 + lk];
        float4 a1 = *(const float4*)&h[(i0 + li) * DIN + k0 + lk + 4];
        float4 a2 = *(const float4*)&h[(i0 + li) * DIN + k0 + lk + 8];
        float4 a3 = *(const float4*)&h[(i0 + li) * DIN + k0 + lk + 12];
        float4 b0 = *(const float4*)&W[(k0 + bk) * DOUT + c0 + bc];
        float4 b1 = *(const float4*)&W[(k0 + bk) * DOUT + c0 + bc + 4];

        __syncthreads();
        As[lk +  0][li] = a0.x; As[lk +  1][li] = a0.y;
        As[lk +  2][li] = a0.z; As[lk +  3][li] = a0.w;
        As[lk +  4][li] = a1.x; As[lk +  5][li] = a1.y;
        As[lk +  6][li] = a1.z; As[lk +  7][li] = a1.w;
        As[lk +  8][li] = a2.x; As[lk +  9][li] = a2.y;
        As[lk + 10][li] = a2.z; As[lk + 11][li] = a2.w;
        As[lk + 12][li] = a3.x; As[lk + 13][li] = a3.y;
        As[lk + 14][li] = a3.z; As[lk + 15][li] = a3.w;
        *(float4*)&Bs[bk][bc]     = b0;
        *(float4*)&Bs[bk][bc + 4] = b1;
        __syncthreads();

        #pragma unroll
        for (int k = 0; k < 32; k++) {
            float4 af0 = *(const float4*)&As[k][ty * 8];
            float4 af1 = *(const float4*)&As[k][ty * 8 + 4];
            float4 bf  = *(const float4*)&Bs[k][tx * 4];
            float ar[8] = {af0.x, af0.y, af0.z, af0.w,
                           af1.x, af1.y, af1.z, af1.w};
            float br[4] = {bf.x, bf.y, bf.z, bf.w};
            #pragma unroll
            for (int r = 0; r < 8; r++)
                #pragma unroll
                for (int c = 0; c < 4; c++)
                    acc[r][c] = fmaf(ar[r], br[c], acc[r][c]);
        }
    }

    #pragma unroll
    for (int r = 0; r < 8; r++) {
        float4 v = make_float4(acc[r][0], acc[r][1], acc[r][2], acc[r][3]);
        *(float4*)&g_hW[(size_t)(i0 + ty * 8 + r) * DOUT + c0 + tx * 4] = v;
    }
    // transposed fp16: 8 rows per column -> one uint4
    #pragma unroll
    for (int cc = 0; cc < 4; cc++) {
        const int c = c0 + tx * 4 + cc;
        uint4 p;
        p.x = pack_f16x2(acc[0][cc], acc[1][cc]);
        p.y = pack_f16x2(acc[2][cc], acc[3][cc]);
        p.z = pack_f16x2(acc[4][cc], acc[5][cc]);
        p.w = pack_f16x2(acc[6][cc], acc[7][cc]);
        *(uint4*)(g_hWT + (size_t)c * NN + i0 + ty * 8) = p;
    }
}

// ---------------------------------------------------------------------------
// Kernel B: f1 = hW @ a[:256],  f2 = hW @ a[256:]
// ---------------------------------------------------------------------------
__global__ void k_f1f2(const float* __restrict__ a)
{
    const int row  = blockIdx.x * 8 + threadIdx.y;
    const int lane = threadIdx.x;
    const float* hw = &g_hW[(size_t)row * DOUT];

    float s1 = 0.f, s2 = 0.f;
    #pragma unroll
    for (int c = 0; c < DOUT; c += 32) {
        float v = hw[c + lane];
        s1 = fmaf(v, a[c + lane], s1);
        s2 = fmaf(v, a[DOUT + c + lane], s2);
    }
    #pragma unroll
    for (int off = 16; off; off >>= 1) {
        s1 += __shfl_xor_sync(0xffffffffu, s1, off);
        s2 += __shfl_xor_sync(0xffffffffu, s2, off);
    }
    if (lane == 0) { g_f1[row] = s1; g_f2[row] = s2; }
}

// ---------------------------------------------------------------------------
// Kernel B2: g_fmax = max(f2)
// ---------------------------------------------------------------------------
__global__ void k_fmax()
{
    __shared__ float sred[32];
    const int tid = threadIdx.x;   // 1024 threads
    float m = -1e30f;
    #pragma unroll
    for (int i = tid; i < NN; i += 1024) m = fmaxf(m, g_f2[i]);
    #pragma unroll
    for (int o = 16; o; o >>= 1) m = fmaxf(m, __shfl_xor_sync(~0u, m, o));
    if ((tid & 31) == 0) sred[tid >> 5] = m;
    __syncthreads();
    if (tid < 32) {
        float v = sred[tid];
        #pragma unroll
        for (int o = 16; o; o >>= 1) v = fmaxf(v, __shfl_xor_sync(~0u, v, o));
        if (tid == 0) g_fmax = v;
    }
}

// ---------------------------------------------------------------------------
// Kernel C: warp-MMA (mma.sync fp16) masked-softmax aggregation.
// M=64 x N=256 CTA tile, 256 threads (8 warps, 2m x 4n), 2 CTAs/SM.
// KT=32 chunks; adj AND B both staged through cp.async double buffers, so
// no DRAM latency is ever exposed and no registers are spent on prefetch.
// A/B SMEM tiles pack two logical rows per 128B physical row (KT=32 ->
// 64B of k per row) so sw128 ldmatrix stays conflict-free.
// ---------------------------------------------------------------------------
// Stage: A 4K | B 16K | adj 64x144B = 9216B  => 30KB (padded), x2 stages
#define ZOFF        0
#define TILE0       2048
#define AOFFB       0
#define BOFFB       4096
#define JOFFB       20480
#define STAGE_BYTES 30720
#define SMEM_TOTAL  (TILE0 + 2 * STAGE_BYTES)
#define ADJ_PITCH   144

__global__ __launch_bounds__(256, 2) void k_gat_mma(const int* __restrict__ adj)
{
    extern __shared__ __align__(1024) char smem[];
    const uint32_t sb = smem_u32(smem);

    const int tid  = threadIdx.x;
    const int lane = tid & 31;
    const int wid  = tid >> 5;
    const int wm   = wid & 1;      // warp row  (32 rows)
    const int wn   = wid >> 1;     // warp col  (64 cols)
    const int i0   = blockIdx.x * 64;
    const int ks   = blockIdx.y;
    const int k0s  = ks * KSL;

    int AOFF[2], BOFF[2], JOFF[2];
    #pragma unroll
    for (int s = 0; s < 2; s++) {
        AOFF[s] = TILE0 + s * STAGE_BYTES + AOFFB;
        BOFF[s] = TILE0 + s * STAGE_BYTES + BOFFB;
        JOFF[s] = TILE0 + s * STAGE_BYTES + JOFFB;
    }

    // ---- w-gen mapping: row iw, 8 k's starting at kb ----
    const int iw = tid >> 2;             // 0..63
    const int kb = (tid & 3) * 8;        // 0,8,16,24
    const float f1v  = g_f1[i0 + iw];
    const float smax = f1v + g_fmax;
    const float Mrow = fmaxf(smax, 0.2f * smax);   // leaky(f1+Fmax) >= all e
    float zacc = 0.f;

    // ---- B cp.async mapping: n-row = tid (0..255), 4 chunks of 16B ----
    const int rB = tid;
    const uint32_t bRowBase = (uint32_t)((rB & 127) * 128 + (rB >> 7) * 64);

    // ---- adj cp.async mapping: row = tid>>2, 32B segment = (tid&3)*32 ----
    const int jr  = tid >> 2;
    const int jsg = (tid & 3) * 8;       // int offset (8 ints = 32B)

    float acc[2][8][4];
    #pragma unroll
    for (int mt = 0; mt < 2; mt++)
        #pragma unroll
        for (int nt = 0; nt < 8; nt++)
            #pragma unroll
            for (int q = 0; q < 4; q++) acc[mt][nt][q] = 0.f;

    auto load_stage = [&](int jt, int s) {
        // B: 64 bytes of k for this n-row
        const size_t gk = (size_t)rB * NN + k0s + jt * KT;
        #pragma unroll
        for (int cc = 0; cc < 4; cc++)
            cp16(sb + BOFF[s] + sw128(bRowBase + cc * 16), g_hWT + gk + cc * 8);
        // adj: 32 bytes (8 ints) of this row's chunk
        const int* asrc = adj + (size_t)(i0 + jr) * NN + k0s + jt * KT + jsg;
        const uint32_t adst = sb + JOFF[s] + jr * ADJ_PITCH + jsg * 4;
        cp16(adst,      asrc);
        cp16(adst + 16, asrc + 4);
    };

    // compute w from SMEM adj + f2 (L1-hot), store fp16 A tile to stage s
    auto gen_A_store = [&](int jt, int s) {
        const int* aj = (const int*)(smem + JOFF[s] + iw * ADJ_PITCH) + kb;
        int4 A0 = *(const int4*)(aj);
        int4 A1 = *(const int4*)(aj + 4);
        const float4* fp = (const float4*)(g_f2 + k0s + jt * KT + kb);
        float4 F0 = fp[0], F1 = fp[1];
        const int   av[8] = {A0.x, A0.y, A0.z, A0.w, A1.x, A1.y, A1.z, A1.w};
        const float fv[8] = {F0.x, F0.y, F0.z, F0.w, F1.x, F1.y, F1.z, F1.w};
        float w[8];
        #pragma unroll
        for (int q = 0; q < 8; q++) {
            float sv = f1v + fv[q];
            float e  = fmaxf(sv, 0.2f * sv);     // leaky
            float we = __expf(e - Mrow);         // in (0,1]
            w[q] = (av[q] > 0) ? we : 0.f;
            zacc += w[q];
        }
        uint4 H;
        H.x = pack_f16x2(w[0], w[1]);
        H.y = pack_f16x2(w[2], w[3]);
        H.z = pack_f16x2(w[4], w[5]);
        H.w = pack_f16x2(w[6], w[7]);
        const uint32_t off = sw128((uint32_t)(
            (iw & 31) * 128 + (iw >> 5) * 64 + kb * 2));
        *(uint4*)(smem + AOFF[s] + off) = H;
    };

    // ldmatrix lane address components
    const int aRow = lane & 15;                        // A: row within 16-tile
    const int aH   = lane >> 4;                        // A: k-half
    const int bRow = (lane & 7) | ((lane >> 4) << 3);  // B: n-row within 16
    const int bH   = (lane >> 3) & 1;                  // B: k-half

    // ---- prologue: fill stage 0 ----
    load_stage(0, 0);
    cp_commit();
    cp_wait0();
    __syncthreads();
    gen_A_store(0, 0);
    __syncthreads();

    #pragma unroll 1
    for (int jt = 0; jt < NCHUNK; ++jt) {
        const int s = jt & 1;
        if (jt + 1 < NCHUNK) {
            load_stage(jt + 1, s ^ 1);   // cp.async B+adj -> stage s^1
            cp_commit();
        }

        // ---- MMA on stage s (hides the cp.async DRAM latency) ----
        #pragma unroll
        for (int kk = 0; kk < 2; kk++) {
            uint32_t ah[2][4];
            #pragma unroll
            for (int mt = 0; mt < 2; mt++) {
                const int m = wm * 32 + mt * 16 + aRow;
                ldsm4(ah[mt], sb + AOFF[s] + sw128((uint32_t)(
                    (m & 31) * 128 + (m >> 5) * 64 + kk * 32 + aH * 16)));
            }
            uint32_t bh[4][4];
            #pragma unroll
            for (int p = 0; p < 4; p++) {
                const int n = wn * 64 + p * 16 + bRow;
                ldsm4(bh[p], sb + BOFF[s] + sw128((uint32_t)(
                    (n & 127) * 128 + (n >> 7) * 64 + kk * 32 + bH * 16)));
            }
            #pragma unroll
            for (int mt = 0; mt < 2; mt++)
                #pragma unroll
                for (int p = 0; p < 4; p++) {
                    mma16816(acc[mt][2 * p],     ah[mt], bh[p][0], bh[p][1]);
                    mma16816(acc[mt][2 * p + 1], ah[mt], bh[p][2], bh[p][3]);
                }
        }

        if (jt + 1 < NCHUNK) {
            cp_wait0();                   // B+adj for s^1 arrived (this thread)
            __syncthreads();              // ... and all threads'
            gen_A_store(jt + 1, s ^ 1);   // reads adjS, writes A s^1
        }
        __syncthreads();                  // A s^1 visible before next MMA
    }

    // ---- epilogue: partial numerators + partial Z ----
    {
        float* npb = g_np + (size_t)ks * NN * DOUT;
        const int g  = lane >> 2;
        const int tg = lane & 3;
        #pragma unroll
        for (int mt = 0; mt < 2; mt++)
            #pragma unroll
            for (int nt = 0; nt < 8; nt++) {
                const int r0  = i0 + wm * 32 + mt * 16 + g;
                const int col = wn * 64 + nt * 8 + tg * 2;
                *(float2*)(npb + (size_t)r0 * DOUT + col) =
                    make_float2(acc[mt][nt][0], acc[mt][nt][1]);
                *(float2*)(npb + (size_t)(r0 + 8) * DOUT + col) =
                    make_float2(acc[mt][nt][2], acc[mt][nt][3]);
            }
    }
    float* zb = (float*)(smem + ZOFF);
    zb[tid] = zacc;
    __syncthreads();
    if (tid < 64)
        g_zp[ks * NN + i0 + tid] =
            zb[4 * tid] + zb[4 * tid + 1] + zb[4 * tid + 2] + zb[4 * tid + 3];
}

// ---------------------------------------------------------------------------
// Kernel D: combine partials, softmax-normalize, ELU
// ---------------------------------------------------------------------------
__global__ void k_combine(float* __restrict__ out)
{
    const int row = blockIdx.x;
    const int c = threadIdx.x * 4;
    const float inv = 1.f / (g_zp[row] + g_zp[NN + row]);
    float4 p0 = *(const float4*)&g_np[(size_t)row * DOUT + c];
    float4 p1 = *(const float4*)&g_np[(size_t)(NN + row) * DOUT + c];
    float v[4] = {(p0.x + p1.x) * inv, (p0.y + p1.y) * inv,
                  (p0.z + p1.z) * inv, (p0.w + p1.w) * inv};
    #pragma unroll
    for (int q = 0; q < 4; q++)
        v[q] = (v[q] > 0.f) ? v[q] : expm1f(v[q]);
    *(float4*)&out[(size_t)row * DOUT + c] = make_float4(v[0], v[1], v[2], v[3]);
}

// ---------------------------------------------------------------------------
extern "C" void kernel_launch(void* const* d_in, const int* in_sizes, int n_in,
                              void* d_out, int out_size)
{
    const float* h   = (const float*)d_in[0];   // [8192, 512]
    const int*   adj = (const int*)  d_in[1];   // [8192, 8192]
    const float* W   = (const float*)d_in[2];   // [512, 256]
    const float* a   = (const float*)d_in[3];   // [512, 1]
    float* out = (float*)d_out;                 // [8192, 256]

    cudaFuncSetAttribute(k_gat_mma, cudaFuncAttributeMaxDynamicSharedMemorySize,
                         SMEM_TOTAL);

    k_gemm_hw<<<dim3(DOUT / 64, NN / 128), 256>>>(h, W);
    k_f1f2<<<NN / 8, dim3(32, 8)>>>(a);
    k_fmax<<<1, 1024>>>();
    k_gat_mma<<<dim3(NN / 64, KSLICES), 256, SMEM_TOTAL>>>(adj);
    k_combine<<<NN, 64>>>(out);
}

// round 8
// speedup vs baseline: 1.1232x; 1.1232x over previous
#include <cuda_runtime.h>
#include <cuda_bf16.h>
#include <cstdint>

#define NN   8192
#define DIN  512
#define DOUT 256
#define KSLICES 2
#define KSL  (NN / KSLICES)     // 4096 k per slice
#define KT   64                 // k per chunk
#define NCHUNK (KSL / KT)       // 64

// ---------------- scratch (__device__ globals: allocation-free rule) --------
__device__ float          g_hW  [(size_t)NN * DOUT];      // fp32 hW (for f1f2)
__device__ float          g_f1  [NN];
__device__ float          g_f2  [NN];
__device__ float          g_fmax;
__device__ unsigned short g_hWT [(size_t)DOUT * NN];      // hW^T fp16 [col][row]
__device__ float          g_np  [(size_t)KSLICES * NN * DOUT]; // partial numerators
__device__ float          g_zp  [KSLICES * NN];                // partial Z

// ---------------- helpers ---------------------------------------------------
__device__ __forceinline__ uint32_t smem_u32(const void* p) {
    uint32_t a;
    asm("{ .reg .u64 t; cvta.to.shared.u64 t, %1; cvt.u32.u64 %0, t; }"
        : "=r"(a) : "l"(p));
    return a;
}
__device__ __forceinline__ uint32_t sw128(uint32_t off) {
    return off ^ ((off >> 3) & 0x70);
}
// packs (lo, hi) -> low 16 = f16(lo), high 16 = f16(hi)
__device__ __forceinline__ unsigned pack_f16x2(float lo, float hi) {
    unsigned r;
    asm("cvt.rn.f16x2.f32 %0, %1, %2;" : "=r"(r) : "f"(hi), "f"(lo));
    return r;
}
__device__ __forceinline__ void cp16(uint32_t smem, const void* g) {
    asm volatile("cp.async.cg.shared.global [%0], [%1], 16;"
                 :: "r"(smem), "l"(g));
}
__device__ __forceinline__ void cp_commit() {
    asm volatile("cp.async.commit_group;");
}
__device__ __forceinline__ void cp_wait0() {
    asm volatile("cp.async.wait_group 0;" ::: "memory");
}
__device__ __forceinline__ void ldsm4(uint32_t* r, uint32_t addr) {
    asm volatile("ldmatrix.sync.aligned.m8n8.x4.shared.b16 {%0,%1,%2,%3}, [%4];"
                 : "=r"(r[0]), "=r"(r[1]), "=r"(r[2]), "=r"(r[3]) : "r"(addr));
}
__device__ __forceinline__ void mma16816(float* c, const uint32_t* a,
                                         uint32_t b0, uint32_t b1) {
    asm volatile(
        "mma.sync.aligned.m16n8k16.row.col.f32.f16.f16.f32 "
        "{%0,%1,%2,%3},{%4,%5,%6,%7},{%8,%9},{%0,%1,%2,%3};"
        : "+f"(c[0]), "+f"(c[1]), "+f"(c[2]), "+f"(c[3])
        : "r"(a[0]), "r"(a[1]), "r"(a[2]), "r"(a[3]), "r"(b0), "r"(b1));
}

// ---------------------------------------------------------------------------
// Kernel A: g_hW = h @ W  (fp32)  +  epilogue: g_hWT fp16 (transposed)
// 128x64 tile, 256 threads, 8x4 micro-tile.
// ---------------------------------------------------------------------------
__global__ __launch_bounds__(256) void k_gemm_hw(
    const float* __restrict__ h, const float* __restrict__ W)
{
    __shared__ float As[32][128];  // [k][m] 16 KB
    __shared__ float Bs[32][64];   // [k][n]  8 KB

    const int tid = threadIdx.x;
    const int c0  = blockIdx.x * 64;
    const int i0  = blockIdx.y * 128;
    const int tx  = tid & 15;            // 4 cols
    const int ty  = tid >> 4;            // 8 rows

    const int li  = tid >> 1;            // 0..127 A-load row
    const int lk  = (tid & 1) * 16;      // A-load k base (16 k's)

    const int bk  = tid >> 3;            // 0..31  B-load k
    const int bc  = (tid & 7) * 8;       // B-load col (8 cols)

    float acc[8][4] = {};

    for (int k0 = 0; k0 < DIN; k0 += 32) {
        float4 a0 = *(const float4*)&h[(i0 + li) * DIN + k0 + lk];
        float4 a1 = *(const float4*)&h[(i0 + li) * DIN + k0 + lk + 4];
        float4 a2 = *(const float4*)&h[(i0 + li) * DIN + k0 + lk + 8];
        float4 a3 = *(const float4*)&h[(i0 + li) * DIN + k0 + lk + 12];
        float4 b0 = *(const float4*)&W[(k0 + bk) * DOUT + c0 + bc];
        float4 b1 = *(const float4*)&W[(k0 + bk) * DOUT + c0 + bc + 4];

        __syncthreads();
        As[lk +  0][li] = a0.x; As[lk +  1][li] = a0.y;
        As[lk +  2][li] = a0.z; As[lk +  3][li] = a0.w;
        As[lk +  4][li] = a1.x; As[lk +  5][li] = a1.y;
        As[lk +  6][li] = a1.z; As[lk +  7][li] = a1.w;
        As[lk +  8][li] = a2.x; As[lk +  9][li] = a2.y;
        As[lk + 10][li] = a2.z; As[lk + 11][li] = a2.w;
        As[lk + 12][li] = a3.x; As[lk + 13][li] = a3.y;
        As[lk + 14][li] = a3.z; As[lk + 15][li] = a3.w;
        *(float4*)&Bs[bk][bc]     = b0;
        *(float4*)&Bs[bk][bc + 4] = b1;
        __syncthreads();

        #pragma unroll
        for (int k = 0; k < 32; k++) {
            float4 af0 = *(const float4*)&As[k][ty * 8];
            float4 af1 = *(const float4*)&As[k][ty * 8 + 4];
            float4 bf  = *(const float4*)&Bs[k][tx * 4];
            float ar[8] = {af0.x, af0.y, af0.z, af0.w,
                           af1.x, af1.y, af1.z, af1.w};
            float br[4] = {bf.x, bf.y, bf.z, bf.w};
            #pragma unroll
            for (int r = 0; r < 8; r++)
                #pragma unroll
                for (int c = 0; c < 4; c++)
                    acc[r][c] = fmaf(ar[r], br[c], acc[r][c]);
        }
    }

    #pragma unroll
    for (int r = 0; r < 8; r++) {
        float4 v = make_float4(acc[r][0], acc[r][1], acc[r][2], acc[r][3]);
        *(float4*)&g_hW[(size_t)(i0 + ty * 8 + r) * DOUT + c0 + tx * 4] = v;
    }
    // transposed fp16: 8 rows per column -> one uint4
    #pragma unroll
    for (int cc = 0; cc < 4; cc++) {
        const int c = c0 + tx * 4 + cc;
        uint4 p;
        p.x = pack_f16x2(acc[0][cc], acc[1][cc]);
        p.y = pack_f16x2(acc[2][cc], acc[3][cc]);
        p.z = pack_f16x2(acc[4][cc], acc[5][cc]);
        p.w = pack_f16x2(acc[6][cc], acc[7][cc]);
        *(uint4*)(g_hWT + (size_t)c * NN + i0 + ty * 8) = p;
    }
}

// ---------------------------------------------------------------------------
// Kernel B: f1 = hW @ a[:256],  f2 = hW @ a[256:]
// ---------------------------------------------------------------------------
__global__ void k_f1f2(const float* __restrict__ a)
{
    const int row  = blockIdx.x * 8 + threadIdx.y;
    const int lane = threadIdx.x;
    const float* hw = &g_hW[(size_t)row * DOUT];

    float s1 = 0.f, s2 = 0.f;
    #pragma unroll
    for (int c = 0; c < DOUT; c += 32) {
        float v = hw[c + lane];
        s1 = fmaf(v, a[c + lane], s1);
        s2 = fmaf(v, a[DOUT + c + lane], s2);
    }
    #pragma unroll
    for (int off = 16; off; off >>= 1) {
        s1 += __shfl_xor_sync(0xffffffffu, s1, off);
        s2 += __shfl_xor_sync(0xffffffffu, s2, off);
    }
    if (lane == 0) { g_f1[row] = s1; g_f2[row] = s2; }
}

// ---------------------------------------------------------------------------
// Kernel B2: g_fmax = max(f2)
// ---------------------------------------------------------------------------
__global__ void k_fmax()
{
    __shared__ float sred[32];
    const int tid = threadIdx.x;   // 1024 threads
    float m = -1e30f;
    #pragma unroll
    for (int i = tid; i < NN; i += 1024) m = fmaxf(m, g_f2[i]);
    #pragma unroll
    for (int o = 16; o; o >>= 1) m = fmaxf(m, __shfl_xor_sync(~0u, m, o));
    if ((tid & 31) == 0) sred[tid >> 5] = m;
    __syncthreads();
    if (tid < 32) {
        float v = sred[tid];
        #pragma unroll
        for (int o = 16; o; o >>= 1) v = fmaxf(v, __shfl_xor_sync(~0u, v, o));
        if (tid == 0) g_fmax = v;
    }
}

// ---------------------------------------------------------------------------
// Kernel C: warp-MMA (mma.sync fp16) masked-softmax aggregation.
// M=64 x N=256 CTA tile, 512 threads (16 warps, 4m x 4n of 16x64 tiles).
// acc = 32 regs/thread -> headroom for adj register-prefetch: the LDG for
// chunk jt+1 is issued BEFORE the MMA loop on jt and consumed after it.
// Single __syncthreads per chunk (R5 structure).
// ---------------------------------------------------------------------------
// SMEM: [0..2KB) zbuf; stages at 2KB: per stage A 8K | B 32K
#define ZOFF        0
#define TILE0       2048
#define STAGE_BYTES 40960
#define SMEM_TOTAL  (TILE0 + 2 * STAGE_BYTES)

__global__ __launch_bounds__(512, 1) void k_gat_mma(const int* __restrict__ adj)
{
    extern __shared__ __align__(1024) char smem[];
    const uint32_t sb = smem_u32(smem);

    const int tid  = threadIdx.x;
    const int lane = tid & 31;
    const int wid  = tid >> 5;     // 0..15
    const int wm   = wid & 3;      // warp m-tile (16 rows)
    const int wn   = wid >> 2;     // warp n-tile (64 cols)
    const int i0   = blockIdx.x * 64;
    const int ks   = blockIdx.y;
    const int k0s  = ks * KSL;

    int AOFF[2], BOFF[2];
    #pragma unroll
    for (int s = 0; s < 2; s++) {
        AOFF[s] = TILE0 + s * STAGE_BYTES;
        BOFF[s] = AOFF[s] + 8192;
    }

    // ---- w-gen mapping: row iw, 8 k's starting at kb ----
    const int iw = tid >> 3;             // 0..63
    const int kb = (tid & 7) * 8;        // 0..56
    const float f1v  = g_f1[i0 + iw];
    const float smax = f1v + g_fmax;
    const float Mrow = fmaxf(smax, 0.2f * smax);   // leaky(f1+Fmax) >= all e
    float zacc = 0.f;

    // ---- B cp.async mapping: n-row = tid>>1 (0..255), 4 chunks of 16B ----
    const int rB   = tid >> 1;
    const int half = (tid & 1) * 4;

    float acc[8][4];
    #pragma unroll
    for (int nt = 0; nt < 8; nt++)
        #pragma unroll
        for (int q = 0; q < 4; q++) acc[nt][q] = 0.f;

    auto load_B = [&](int jt, int s) {
        const size_t gk = (size_t)rB * NN + k0s + jt * KT;
        #pragma unroll
        for (int c = 0; c < 4; c++) {
            const int cc = half + c;
            const uint32_t off = sw128((uint32_t)(rB * 128 + cc * 16));
            cp16(sb + BOFF[s] + off, g_hWT + gk + cc * 8);
        }
    };

    // adj prefetch registers (8 ints, live across MMA loop)
    int4 pa0, pa1;
    auto prefetch_adj = [&](int jt) {
        const int4* ap = (const int4*)(adj + (size_t)(i0 + iw) * NN
                                       + k0s + jt * KT + kb);
        pa0 = ap[0]; pa1 = ap[1];
    };

    // consume prefetched adj, compute w, store fp16 A row-segment to stage s
    auto gen_A_store = [&](int jt, int s) {
        const float4* fp = (const float4*)(g_f2 + k0s + jt * KT + kb);
        float4 F0 = fp[0], F1 = fp[1];
        const int   av[8] = {pa0.x, pa0.y, pa0.z, pa0.w,
                             pa1.x, pa1.y, pa1.z, pa1.w};
        const float fv[8] = {F0.x, F0.y, F0.z, F0.w, F1.x, F1.y, F1.z, F1.w};
        float w[8];
        #pragma unroll
        for (int q = 0; q < 8; q++) {
            float sv = f1v + fv[q];
            float e  = fmaxf(sv, 0.2f * sv);     // leaky
            float we = __expf(e - Mrow);         // in (0,1]
            w[q] = (av[q] > 0) ? we : 0.f;
            zacc += w[q];
        }
        uint4 H;
        H.x = pack_f16x2(w[0], w[1]);
        H.y = pack_f16x2(w[2], w[3]);
        H.z = pack_f16x2(w[4], w[5]);
        H.w = pack_f16x2(w[6], w[7]);
        const uint32_t off = sw128((uint32_t)(iw * 128 + kb * 2));
        *(uint4*)(smem + AOFF[s] + off) = H;
    };

    // ldmatrix lane address components
    const int aRow = lane & 15;                        // A: row within 16-tile
    const int aH   = lane >> 4;                        // A: k-half
    const int bRow = (lane & 7) | ((lane >> 4) << 3);  // B: n-row within 16
    const int bH   = (lane >> 3) & 1;                  // B: k-half

    // ---- prologue: fill stage 0 ----
    load_B(0, 0);
    cp_commit();
    prefetch_adj(0);
    gen_A_store(0, 0);
    cp_wait0();
    __syncthreads();

    #pragma unroll 1
    for (int jt = 0; jt < NCHUNK; ++jt) {
        const int s = jt & 1;
        if (jt + 1 < NCHUNK) {
            load_B(jt + 1, s ^ 1);   // cp.async B -> stage s^1
            cp_commit();
            prefetch_adj(jt + 1);    // LDG -> 8 regs, consumed AFTER MMAs
        }

        // ---- MMA on stage s (hides the adj LDG + cp.async latency) ----
        #pragma unroll
        for (int kk = 0; kk < 4; kk++) {
            uint32_t ah[4];
            ldsm4(ah, sb + AOFF[s] + sw128((uint32_t)(
                (wm * 16 + aRow) * 128 + kk * 32 + aH * 16)));
            uint32_t bh[4][4];
            #pragma unroll
            for (int p = 0; p < 4; p++)
                ldsm4(bh[p], sb + BOFF[s] + sw128((uint32_t)(
                    (wn * 64 + p * 16 + bRow) * 128 + kk * 32 + bH * 16)));
            #pragma unroll
            for (int p = 0; p < 4; p++) {
                mma16816(acc[2 * p],     ah, bh[p][0], bh[p][1]);
                mma16816(acc[2 * p + 1], ah, bh[p][2], bh[p][3]);
            }
        }

        if (jt + 1 < NCHUNK) {
            gen_A_store(jt + 1, s ^ 1);   // consume regs, fill A stage s^1
            cp_wait0();                   // B stage s^1 arrived
        }
        __syncthreads();
    }

    // ---- epilogue: partial numerators + partial Z ----
    {
        float* npb = g_np + (size_t)ks * NN * DOUT;
        const int g  = lane >> 2;
        const int tg = lane & 3;
        #pragma unroll
        for (int nt = 0; nt < 8; nt++) {
            const int r0  = i0 + wm * 16 + g;
            const int col = wn * 64 + nt * 8 + tg * 2;
            *(float2*)(npb + (size_t)r0 * DOUT + col) =
                make_float2(acc[nt][0], acc[nt][1]);
            *(float2*)(npb + (size_t)(r0 + 8) * DOUT + col) =
                make_float2(acc[nt][2], acc[nt][3]);
        }
    }
    float* zb = (float*)(smem + ZOFF);
    zb[tid] = zacc;
    __syncthreads();
    if (tid < 64) {
        float z = 0.f;
        #pragma unroll
        for (int q = 0; q < 8; q++) z += zb[tid * 8 + q];
        g_zp[ks * NN + i0 + tid] = z;
    }
}

// ---------------------------------------------------------------------------
// Kernel D: combine partials, softmax-normalize, ELU
// ---------------------------------------------------------------------------
__global__ void k_combine(float* __restrict__ out)
{
    const int row = blockIdx.x;
    const int c = threadIdx.x * 4;
    const float inv = 1.f / (g_zp[row] + g_zp[NN + row]);
    float4 p0 = *(const float4*)&g_np[(size_t)row * DOUT + c];
    float4 p1 = *(const float4*)&g_np[(size_t)(NN + row) * DOUT + c];
    float v[4] = {(p0.x + p1.x) * inv, (p0.y + p1.y) * inv,
                  (p0.z + p1.z) * inv, (p0.w + p1.w) * inv};
    #pragma unroll
    for (int q = 0; q < 4; q++)
        v[q] = (v[q] > 0.f) ? v[q] : expm1f(v[q]);
    *(float4*)&out[(size_t)row * DOUT + c] = make_float4(v[0], v[1], v[2], v[3]);
}

// ---------------------------------------------------------------------------
extern "C" void kernel_launch(void* const* d_in, const int* in_sizes, int n_in,
                              void* d_out, int out_size)
{
    const float* h   = (const float*)d_in[0];   // [8192, 512]
    const int*   adj = (const int*)  d_in[1];   // [8192, 8192]
    const float* W   = (const float*)d_in[2];   // [512, 256]
    const float* a   = (const float*)d_in[3];   // [512, 1]
    float* out = (float*)d_out;                 // [8192, 256]

    cudaFuncSetAttribute(k_gat_mma, cudaFuncAttributeMaxDynamicSharedMemorySize,
                         SMEM_TOTAL);

    k_gemm_hw<<<dim3(DOUT / 64, NN / 128), 256>>>(h, W);
    k_f1f2<<<NN / 8, dim3(32, 8)>>>(a);
    k_fmax<<<1, 1024>>>();
    k_gat_mma<<<dim3(NN / 64, KSLICES), 512, SMEM_TOTAL>>>(adj);
    k_combine<<<NN, 64>>>(out);
}